// round 7
// baseline (speedup 1.0000x reference)
#include <cuda_runtime.h>
#include <math.h>

#define BB 8
#define TT 1024
#define DD 128
#define UU 2048
#define OUTF (DD + UU)
#define NCTA 128
#define COLS 16
#define NTHR 1024
#define NWARP 32

typedef unsigned long long ull;

// SMEM layout (floats)
#define W_FLOATS   (UU * COLS)    // 32768  w_res slice [2048][16], 64B rows, chunk-swizzled
#define S_FLOATS   (UU * BB)      // 16384  state [2048][8], 16B-granule swizzled
#define WI_FLOATS  (DD * COLS)    // 2048   w_in slice, same swizzle as w
#define BI_FLOATS  16
#define RED_ULL    (NWARP * 16)   // [32 warps][16] f32x2 warp partials
#define SMEM_FLOATS (W_FLOATS + S_FLOATS + WI_FLOATS + BI_FLOATS + RED_ULL * 2)
#define SMEM_BYTES  (SMEM_FLOATS * 4)   // ~209 KB < 227 KB

__device__ float g_state[2][UU * BB];   // ping-pong state, linear [k][b]
__device__ unsigned g_bar_count;        // init-barrier
__device__ unsigned g_bar_gen;          // monotone across replays
__device__ unsigned g_step_count;       // per-step arrivals (64/CTA), reset each launch

__device__ __forceinline__ void cp16(unsigned dst, const void* src) {
    asm volatile("cp.async.cg.shared.global [%0], [%1], 16;" :: "r"(dst), "l"(src));
}
__device__ __forceinline__ void cp_commit() { asm volatile("cp.async.commit_group;"); }
template <int N>
__device__ __forceinline__ void cp_wait() {
    asm volatile("cp.async.wait_group %0;" :: "n"(N));
}
// packed fp32x2 ops — ptxas never emits these from C++
__device__ __forceinline__ void ffma2(ull& acc, ull a, ull b) {
    asm("fma.rn.f32x2 %0, %1, %2, %0;" : "+l"(acc) : "l"(a), "l"(b));
}
__device__ __forceinline__ ull dup2(float x) {
    ull r;
    unsigned xi = __float_as_uint(x);
    asm("mov.b64 %0, {%1, %1};" : "=l"(r) : "r"(xi));
    return r;
}
__device__ __forceinline__ ull padd2(ull a, ull b) {
    ull r;
    asm("add.rn.f32x2 %0, %1, %2;" : "=l"(r) : "l"(a), "l"(b));
    return r;
}
__device__ __forceinline__ ull bfly2(ull v, int m) {
    unsigned lo = (unsigned)v, hi = (unsigned)(v >> 32);
    lo = __shfl_xor_sync(0xffffffffu, lo, m);
    hi = __shfl_xor_sync(0xffffffffu, hi, m);
    ull r;
    asm("mov.b64 %0, {%1, %2};" : "=l"(r) : "r"(lo), "r"(hi));
    return r;
}

// init-only grid barrier (proven pattern)
__device__ __forceinline__ void grid_barrier_init() {
    __syncthreads();
    if (threadIdx.x == 0) {
        __threadfence();
        unsigned gen;
        asm volatile("ld.acquire.gpu.u32 %0, [%1];" : "=r"(gen) : "l"(&g_bar_gen));
        if (atomicAdd(&g_bar_count, 1) == NCTA - 1) {
            g_bar_count = 0;
            asm volatile("st.release.gpu.u32 [%0], %1;" :: "l"(&g_bar_gen), "r"(gen + 1)
                         : "memory");
        } else {
            unsigned cur;
            do {
                asm volatile("ld.acquire.gpu.u32 %0, [%1];" : "=r"(cur) : "l"(&g_bar_gen));
                if (cur != gen) break;
                __nanosleep(32);
            } while (true);
        }
    }
    __syncthreads();
}

__global__ void __launch_bounds__(NTHR, 1)
esn_kernel(const float* __restrict__ inputs, const float* __restrict__ w_in_g,
           const float* __restrict__ b_in_g, const float* __restrict__ w_res_g,
           float* __restrict__ out) {
    extern __shared__ float smem[];
    float* w_sh  = smem;                    // [2048][16]
    float* s_sh  = w_sh + W_FLOATS;         // [2048][8] swizzled
    float* wi_sh = s_sh + S_FLOATS;         // [128][16]
    float* bi_sh = wi_sh + WI_FLOATS;       // [16]
    ull* red = (ull*)(bi_sh + BI_FLOATS);   // [32 warps][16]

    const int tid = threadIdx.x;
    const int cta = blockIdx.x;
    const int col0 = cta * COLS;

    if (cta == 0 && tid == 0) g_step_count = 0;   // fresh epoch per launch/replay

    // Stage w_res slice; 16B chunk c of row r stored at position c ^ ((r>>1)&3)
    for (int r = tid; r < UU; r += NTHR) {
        const float4* src = (const float4*)(w_res_g + (size_t)r * UU + col0);
        int m = (r >> 1) & 3;
        float4* dst = (float4*)(w_sh + r * COLS);
        dst[0 ^ m] = src[0]; dst[1 ^ m] = src[1];
        dst[2 ^ m] = src[2]; dst[3 ^ m] = src[3];
    }
    if (tid < DD) {
        int r = tid;
        const float4* src = (const float4*)(w_in_g + (size_t)r * UU + col0);
        int m = (r >> 1) & 3;
        float4* dst = (float4*)(wi_sh + r * COLS);
        dst[0 ^ m] = src[0]; dst[1 ^ m] = src[1];
        dst[2 ^ m] = src[2]; dst[3 ^ m] = src[3];
    }
    if (tid < COLS) bi_sh[tid] = b_in_g[col0 + tid];

    // Zero initial state (buffer 0)
    for (int i = cta * NTHR + tid; i < UU * BB; i += NCTA * NTHR) g_state[0][i] = 0.0f;

    grid_barrier_init();

    // Decomposition: 256 k-slices x 2 col-halves x 2 batch-halves
    const int ks = tid & 255;
    const int bh = (tid >> 8) & 1;
    const int jh = tid >> 9;
    const int mk = (ks >> 1) & 3;            // weight swizzle key (thread-const)
    const unsigned w_off0 = (unsigned)(4 * ks + ((2 * jh) ^ mk)) * 16;
    const unsigned w_off1 = (unsigned)(4 * ks + ((2 * jh + 1) ^ mk)) * 16;
    const unsigned Gs = (unsigned)(2 * ks + bh);
    const unsigned s_off = (Gs ^ ((Gs >> 3) & 1)) * 16;   // state swizzle (thread-const)
    const int warp = tid >> 5;
    const int lane = tid & 31;
    const int brev = ((lane & 1) << 3) | ((lane & 2) << 1) |
                     ((lane & 4) >> 1) | ((lane & 8) >> 3);
    const unsigned s_base = (unsigned)__cvta_generic_to_shared(s_sh);

    for (int t = 0; t < TT; ++t) {
        // x_t (4 batches of this thread's bh-half); independent of state
        float xv[4];
        if (ks < DD) {
#pragma unroll
            for (int b = 0; b < 4; ++b)
                xv[b] = __ldg(inputs + ((size_t)((bh * 4 + b) * TT + t)) * DD + ks);
        }

        // Step gate: all 128 CTAs x 64 epilogue-releases for step t-1
        if (tid == 0) {
            const unsigned target = 8192u * (unsigned)t;
            unsigned v;
            do {
                asm volatile("ld.acquire.gpu.global.u32 %0, [%1];"
                             : "=r"(v) : "l"(&g_step_count));
            } while (v < target);
        }
        __syncthreads();

        // Broadcast state: 4 chunks x 16KB; granule g stored at g ^ ((g>>3)&1)
        const float* sg = g_state[t & 1];
#pragma unroll
        for (int c = 0; c < 4; ++c) {
            int g = c * 1024 + tid;
            cp16(s_base + ((unsigned)(g ^ ((g >> 3) & 1)) << 4), sg + g * 4);
            cp_commit();
        }

        ull acc[4][4];
#pragma unroll
        for (int a1 = 0; a1 < 4; ++a1)
#pragma unroll
            for (int a2 = 0; a2 < 4; ++a2) acc[a1][a2] = 0ULL;

        // Input projection (overlaps chunk-0 flight); wi has same swizzle as w
        if (ks < DD) {
            ulonglong2 u0 = *(const ulonglong2*)((const char*)wi_sh + w_off0);
            ulonglong2 u1 = *(const ulonglong2*)((const char*)wi_sh + w_off1);
#pragma unroll
            for (int b = 0; b < 4; ++b) {
                ull d = dup2(xv[b]);
                ffma2(acc[b][0], u0.x, d); ffma2(acc[b][1], u0.y, d);
                ffma2(acc[b][2], u1.x, d); ffma2(acc[b][3], u1.y, d);
            }
        }

#define ROW(i)                                                                        \
    {                                                                                 \
        float4 s = *(const float4*)((const char*)s_sh + s_off + (i) * 8192);          \
        ulonglong2 u0 = *(const ulonglong2*)((const char*)w_sh + w_off0 + (i) * 16384); \
        ulonglong2 u1 = *(const ulonglong2*)((const char*)w_sh + w_off1 + (i) * 16384); \
        ull d;                                                                        \
        d = dup2(s.x);                                                                \
        ffma2(acc[0][0], u0.x, d); ffma2(acc[0][1], u0.y, d);                         \
        ffma2(acc[0][2], u1.x, d); ffma2(acc[0][3], u1.y, d);                         \
        d = dup2(s.y);                                                                \
        ffma2(acc[1][0], u0.x, d); ffma2(acc[1][1], u0.y, d);                         \
        ffma2(acc[1][2], u1.x, d); ffma2(acc[1][3], u1.y, d);                         \
        d = dup2(s.z);                                                                \
        ffma2(acc[2][0], u0.x, d); ffma2(acc[2][1], u0.y, d);                         \
        ffma2(acc[2][2], u1.x, d); ffma2(acc[2][3], u1.y, d);                         \
        d = dup2(s.w);                                                                \
        ffma2(acc[3][0], u0.x, d); ffma2(acc[3][1], u0.y, d);                         \
        ffma2(acc[3][2], u1.x, d); ffma2(acc[3][3], u1.y, d);                         \
    }

        // Pipelined dot: chunk c holds rows 512c..512c+511 = i = 2c, 2c+1
        cp_wait<3>(); __syncthreads();
        ROW(0) ROW(1)
        cp_wait<2>(); __syncthreads();
        ROW(2) ROW(3)
        cp_wait<1>(); __syncthreads();
        ROW(4) ROW(5)
        cp_wait<0>(); __syncthreads();
        ROW(6) ROW(7)
#undef ROW

        // Warp butterfly: 16 accs/lane -> 1; lane L (<16) holds acc index brev4(L)
        {
            ull* A = &acc[0][0];
#pragma unroll
            for (int lev = 0; lev < 4; ++lev) {
                const int mm = 1 << lev;
                const int n = 8 >> lev;
                const bool up = (lane & mm) != 0;
#pragma unroll
                for (int q = 0; q < n; ++q) {
                    ull send = up ? A[q] : A[q + n];
                    ull recv = bfly2(send, mm);
                    ull keep = up ? A[q + n] : A[q];
                    A[q] = padd2(keep, recv);
                }
            }
            A[0] = padd2(A[0], bfly2(A[0], 16));
            if (lane < 16) red[warp * 16 + brev] = A[0];
        }
        __syncthreads();

        // Final reduce over 8 warps per (jh,bh) + epilogue (64 threads)
        if (tid < 64) {
            const int a = tid & 15;
            const int bh2 = (tid >> 4) & 1;
            const int jh2 = tid >> 5;
            const int wb = jh2 * 16 + bh2 * 8;
            ull v = red[wb * 16 + a];
#pragma unroll
            for (int w = 1; w < 8; ++w) v = padd2(v, red[(wb + w) * 16 + a]);
            const int b = bh2 * 4 + (a >> 2);
            const int jl = jh2 * 8 + (a & 3) * 2;
            const int c0 = col0 + jl;
            float pre0 = __uint_as_float((unsigned)v) + bi_sh[jl];
            float pre1 = __uint_as_float((unsigned)(v >> 32)) + bi_sh[jl + 1];
            // old state from swizzled SMEM
            unsigned G0 = (unsigned)(2 * c0 + (b >> 2));
            unsigned G1 = G0 + 2;
            float so0 = s_sh[(G0 ^ ((G0 >> 3) & 1)) * 4 + (b & 3)];
            float so1 = s_sh[(G1 ^ ((G1 >> 3) & 1)) * 4 + (b & 3)];
            float n0 = 0.5f * so0 + 0.5f * tanhf(pre0);
            float n1 = 0.5f * so1 + 0.5f * tanhf(pre1);
            float* sn = g_state[(t & 1) ^ 1];      // linear layout in global
            __stcg(sn + c0 * 8 + b, n0);
            __stcg(sn + (c0 + 1) * 8 + b, n1);
            float2 ov;                              // PowerIndex: even col squared
            ov.x = n0 * n0;
            ov.y = n1;
            *(float2*)(out + ((size_t)(b * TT + t)) * OUTF + DD + c0) = ov;
            // per-thread release: orders this thread's stores; 64 arrivals/CTA
            asm volatile("red.release.gpu.global.add.u32 [%0], %1;"
                         :: "l"(&g_step_count), "r"(1u) : "memory");
        }
    }
}

__global__ void copy_inputs_kernel(const float4* __restrict__ in, float* __restrict__ out) {
    int idx = blockIdx.x * blockDim.x + threadIdx.x;
    if (idx < BB * TT * DD / 4) {
        int bt = idx >> 5;  // 32 float4 per (b,t) row
        int q = idx & 31;
        float4 v = in[idx];
        *(float4*)(out + (size_t)bt * OUTF + q * 4) = v;
    }
}

extern "C" void kernel_launch(void* const* d_in, const int* in_sizes, int n_in,
                              void* d_out, int out_size) {
    const float* inputs = (const float*)d_in[0];
    const float* w_in   = (const float*)d_in[1];
    const float* b_in   = (const float*)d_in[2];
    const float* w_res  = (const float*)d_in[3];
    float* out = (float*)d_out;

    cudaFuncSetAttribute(esn_kernel, cudaFuncAttributeMaxDynamicSharedMemorySize, SMEM_BYTES);

    copy_inputs_kernel<<<(BB * TT * DD / 4 + 255) / 256, 256>>>((const float4*)inputs, out);
    esn_kernel<<<NCTA, NTHR, SMEM_BYTES>>>(inputs, w_in, b_in, w_res, out);
}

// round 8
// speedup vs baseline: 1.2166x; 1.2166x over previous
#include <cuda_runtime.h>
#include <math.h>

#define BB 8
#define TT 1024
#define DD 128
#define UU 2048
#define OUTF (DD + UU)
#define NCTA 128
#define COLS 16
#define NTHR 512
#define NWARP 16

typedef unsigned long long ull;

// SMEM layout (floats)
#define W_FLOATS   (UU * COLS)    // 32768  w_res slice, 64B rows, chunk-swizzled
#define S_FLOATS   (UU * BB)      // 16384  state, 16B-granule swizzled
#define WI_FLOATS  (DD * COLS)    // 2048   w_in slice, same swizzle
#define BI_FLOATS  16
#define RED_ULL    (NWARP * 64)   // [16 warps][64 og] f32x2 partials
#define SMEM_FLOATS (W_FLOATS + S_FLOATS + WI_FLOATS + BI_FLOATS + RED_ULL * 2)
#define SMEM_BYTES  (SMEM_FLOATS * 4)   // ~213 KB < 227 KB

__device__ float g_state[2][UU * BB];   // ping-pong state, linear [k][b]
__device__ unsigned g_bar_count;        // init barrier
__device__ unsigned g_bar_gen;          // monotone across replays
__device__ unsigned g_step_count;       // 1 release per CTA per step

__device__ __forceinline__ void cp16(unsigned dst, const void* src) {
    asm volatile("cp.async.cg.shared.global [%0], [%1], 16;" :: "r"(dst), "l"(src));
}
__device__ __forceinline__ void cp_commit() { asm volatile("cp.async.commit_group;"); }
template <int N>
__device__ __forceinline__ void cp_wait() {
    asm volatile("cp.async.wait_group %0;" :: "n"(N));
}
__device__ __forceinline__ void ffma2(ull& acc, ull a, ull b) {
    asm("fma.rn.f32x2 %0, %1, %2, %0;" : "+l"(acc) : "l"(a), "l"(b));
}
__device__ __forceinline__ ull dup2(float x) {
    ull r;
    unsigned xi = __float_as_uint(x);
    asm("mov.b64 %0, {%1, %1};" : "=l"(r) : "r"(xi));
    return r;
}
__device__ __forceinline__ ull padd2(ull a, ull b) {
    ull r;
    asm("add.rn.f32x2 %0, %1, %2;" : "=l"(r) : "l"(a), "l"(b));
    return r;
}
__device__ __forceinline__ ull bfly2(ull v, int m) {
    unsigned lo = (unsigned)v, hi = (unsigned)(v >> 32);
    lo = __shfl_xor_sync(0xffffffffu, lo, m);
    hi = __shfl_xor_sync(0xffffffffu, hi, m);
    ull r;
    asm("mov.b64 %0, {%1, %2};" : "=l"(r) : "r"(lo), "r"(hi));
    return r;
}

// init-only grid barrier (proven pattern)
__device__ __forceinline__ void grid_barrier_init() {
    __syncthreads();
    if (threadIdx.x == 0) {
        __threadfence();
        unsigned gen;
        asm volatile("ld.acquire.gpu.u32 %0, [%1];" : "=r"(gen) : "l"(&g_bar_gen));
        if (atomicAdd(&g_bar_count, 1) == NCTA - 1) {
            g_bar_count = 0;
            asm volatile("st.release.gpu.u32 [%0], %1;" :: "l"(&g_bar_gen), "r"(gen + 1)
                         : "memory");
        } else {
            unsigned cur;
            do {
                asm volatile("ld.acquire.gpu.u32 %0, [%1];" : "=r"(cur) : "l"(&g_bar_gen));
                if (cur != gen) break;
                __nanosleep(32);
            } while (true);
        }
    }
    __syncthreads();
}

__global__ void __launch_bounds__(NTHR, 1)
esn_kernel(const float* __restrict__ inputs, const float* __restrict__ w_in_g,
           const float* __restrict__ b_in_g, const float* __restrict__ w_res_g,
           float* __restrict__ out) {
    extern __shared__ float smem[];
    float* w_sh  = smem;                    // [2048][16] chunk-swizzled
    float* s_sh  = w_sh + W_FLOATS;         // [2048][8] granule-swizzled
    float* wi_sh = s_sh + S_FLOATS;         // [128][16] chunk-swizzled
    float* bi_sh = wi_sh + WI_FLOATS;       // [16]
    ull* red = (ull*)(bi_sh + BI_FLOATS);   // [16 warps][64]

    const int tid = threadIdx.x;
    const int cta = blockIdx.x;
    const int col0 = cta * COLS;

    if (cta == 0 && tid == 0) g_step_count = 0;   // fresh epoch per launch/replay

    // Stage w_res slice; 16B chunk c of row r stored at position c ^ ((r>>1)&3)
    for (int r = tid; r < UU; r += NTHR) {
        const float4* src = (const float4*)(w_res_g + (size_t)r * UU + col0);
        int m = (r >> 1) & 3;
        float4* dst = (float4*)(w_sh + r * COLS);
        dst[0 ^ m] = src[0]; dst[1 ^ m] = src[1];
        dst[2 ^ m] = src[2]; dst[3 ^ m] = src[3];
    }
    if (tid < DD) {
        int r = tid;
        const float4* src = (const float4*)(w_in_g + (size_t)r * UU + col0);
        int m = (r >> 1) & 3;
        float4* dst = (float4*)(wi_sh + r * COLS);
        dst[0 ^ m] = src[0]; dst[1 ^ m] = src[1];
        dst[2 ^ m] = src[2]; dst[3 ^ m] = src[3];
    }
    if (tid < COLS) bi_sh[tid] = b_in_g[col0 + tid];

    // Zero initial state (buffer 0)
    for (int i = cta * NTHR + tid; i < UU * BB; i += NCTA * NTHR) g_state[0][i] = 0.0f;

    grid_barrier_init();

    // Decomposition: pair lanes share a k-slice; jh = column half (8 cols each).
    const int warp = tid >> 5;
    const int lane = tid & 31;
    const int jh = lane & 1;
    const int ks = (warp << 4) + (lane >> 1);     // 0..255
    const int mk = (ks >> 1) & 3;                 // weight chunk-swizzle key
    const unsigned w_off0 = (unsigned)(4 * ks + ((2 * jh) ^ mk)) * 16;
    const unsigned w_off1 = (unsigned)(4 * ks + ((2 * jh + 1) ^ mk)) * 16;
    const unsigned gA = 2 * ks, gB = 2 * ks + 1;  // state granules of row ks
    const unsigned sA_off = (gA ^ ((gA >> 3) & 1)) * 16;
    const unsigned sB_off = (gB ^ ((gB >> 3) & 1)) * 16;
    const unsigned gw = (unsigned)(32 * warp + lane);  // this lane's cp granule base
    // butterfly landing map: lane bit1->+16, bit2->+8, bit3->+4, bit4->+2
    const int base = (((lane >> 1) & 1) << 4) | (((lane >> 2) & 1) << 3) |
                     (((lane >> 3) & 1) << 2) | (((lane >> 4) & 1) << 1);
    const unsigned s_base = (unsigned)__cvta_generic_to_shared(s_sh);

    for (int t = 0; t < TT; ++t) {
        // x_t for proj rows (ks<128); independent of state, in flight over the gate
        float xv[8];
        if (ks < DD) {
#pragma unroll
            for (int b = 0; b < 8; ++b)
                xv[b] = __ldg(inputs + ((size_t)(b * TT + t)) * DD + ks);
        }

        // Step gate: all 128 CTAs released step t-1 (1 release per CTA)
        if (tid == 0) {
            const unsigned target = 128u * (unsigned)t;
            unsigned v;
            do {
                asm volatile("ld.acquire.gpu.global.u32 %0, [%1];"
                             : "=r"(v) : "l"(&g_step_count));
            } while (v < target);
        }
        __syncthreads();

        // Warp-self-sufficient state loads: warp w loads exactly the granules
        // its lanes read (g = 32w + lane + 512i), one commit group per chunk i.
        const float* sg = g_state[t & 1];
#pragma unroll
        for (int i = 0; i < 8; ++i) {
            unsigned g = gw + 512u * i;
            cp16(s_base + ((g ^ ((g >> 3) & 1)) << 4), sg + g * 4);
            cp_commit();
        }

        ull acc[8][4];
#pragma unroll
        for (int a1 = 0; a1 < 8; ++a1)
#pragma unroll
            for (int a2 = 0; a2 < 4; ++a2) acc[a1][a2] = 0ULL;

        // Input projection (overlaps chunk-0 flight); wi row = ks, same offsets
        if (ks < DD) {
            ulonglong2 u0 = *(const ulonglong2*)((const char*)wi_sh + w_off0);
            ulonglong2 u1 = *(const ulonglong2*)((const char*)wi_sh + w_off1);
#pragma unroll
            for (int b = 0; b < 8; ++b) {
                ull d = dup2(xv[b]);
                ffma2(acc[b][0], u0.x, d); ffma2(acc[b][1], u0.y, d);
                ffma2(acc[b][2], u1.x, d); ffma2(acc[b][3], u1.y, d);
            }
        }

#define ROW(i, WN)                                                                     \
    {                                                                                  \
        cp_wait<WN>();                                                                 \
        __syncwarp();                                                                  \
        float4 sA = *(const float4*)((const char*)s_sh + sA_off + (i) * 8192);         \
        float4 sB = *(const float4*)((const char*)s_sh + sB_off + (i) * 8192);         \
        ulonglong2 u0 = *(const ulonglong2*)((const char*)w_sh + w_off0 + (i) * 16384);\
        ulonglong2 u1 = *(const ulonglong2*)((const char*)w_sh + w_off1 + (i) * 16384);\
        ull d;                                                                         \
        d = dup2(sA.x);                                                                \
        ffma2(acc[0][0], u0.x, d); ffma2(acc[0][1], u0.y, d);                          \
        ffma2(acc[0][2], u1.x, d); ffma2(acc[0][3], u1.y, d);                          \
        d = dup2(sA.y);                                                                \
        ffma2(acc[1][0], u0.x, d); ffma2(acc[1][1], u0.y, d);                          \
        ffma2(acc[1][2], u1.x, d); ffma2(acc[1][3], u1.y, d);                          \
        d = dup2(sA.z);                                                                \
        ffma2(acc[2][0], u0.x, d); ffma2(acc[2][1], u0.y, d);                          \
        ffma2(acc[2][2], u1.x, d); ffma2(acc[2][3], u1.y, d);                          \
        d = dup2(sA.w);                                                                \
        ffma2(acc[3][0], u0.x, d); ffma2(acc[3][1], u0.y, d);                          \
        ffma2(acc[3][2], u1.x, d); ffma2(acc[3][3], u1.y, d);                          \
        d = dup2(sB.x);                                                                \
        ffma2(acc[4][0], u0.x, d); ffma2(acc[4][1], u0.y, d);                          \
        ffma2(acc[4][2], u1.x, d); ffma2(acc[4][3], u1.y, d);                          \
        d = dup2(sB.y);                                                                \
        ffma2(acc[5][0], u0.x, d); ffma2(acc[5][1], u0.y, d);                          \
        ffma2(acc[5][2], u1.x, d); ffma2(acc[5][3], u1.y, d);                          \
        d = dup2(sB.z);                                                                \
        ffma2(acc[6][0], u0.x, d); ffma2(acc[6][1], u0.y, d);                          \
        ffma2(acc[6][2], u1.x, d); ffma2(acc[6][3], u1.y, d);                          \
        d = dup2(sB.w);                                                                \
        ffma2(acc[7][0], u0.x, d); ffma2(acc[7][1], u0.y, d);                          \
        ffma2(acc[7][2], u1.x, d); ffma2(acc[7][3], u1.y, d);                          \
    }

        ROW(0, 7) ROW(1, 6) ROW(2, 5) ROW(3, 4)
        ROW(4, 3) ROW(5, 2) ROW(6, 1) ROW(7, 0)
#undef ROW

        // 4-level butterfly over masks 2,4,8,16 (mask 1 = column-half partner,
        // must not be summed). Lane ends with og (jh, base) and (jh, base+1).
        {
            ull* A = &acc[0][0];
#pragma unroll
            for (int lev = 0; lev < 4; ++lev) {
                const int mm = 2 << lev;
                const int n = 16 >> lev;
                const bool up = (lane & mm) != 0;
#pragma unroll
                for (int q = 0; q < n; ++q) {
                    ull send = up ? A[q] : A[q + n];
                    ull recv = bfly2(send, mm);
                    ull keep = up ? A[q + n] : A[q];
                    A[q] = padd2(keep, recv);
                }
            }
            red[warp * 64 + jh * 32 + base] = A[0];
            red[warp * 64 + jh * 32 + base + 1] = A[1];
        }
        __syncthreads();

        // Final reduce over 16 warps + epilogue (64 threads)
        if (tid < 64) {
            ull v = red[tid];
#pragma unroll
            for (int w = 1; w < NWARP; ++w) v = padd2(v, red[w * 64 + tid]);
            const int jh2 = tid >> 5;
            const int a = tid & 31;
            const int b = a >> 2;
            const int p = a & 3;
            const int jl = jh2 * 8 + 2 * p;
            const int c0 = col0 + jl;
            float pre0 = __uint_as_float((unsigned)v) + bi_sh[jl];
            float pre1 = __uint_as_float((unsigned)(v >> 32)) + bi_sh[jl + 1];
            unsigned G0 = (unsigned)(2 * c0 + (b >> 2));
            unsigned G1 = G0 + 2;
            float so0 = s_sh[(G0 ^ ((G0 >> 3) & 1)) * 4 + (b & 3)];
            float so1 = s_sh[(G1 ^ ((G1 >> 3) & 1)) * 4 + (b & 3)];
            float n0 = 0.5f * so0 + 0.5f * tanhf(pre0);
            float n1 = 0.5f * so1 + 0.5f * tanhf(pre1);
            float* sn = g_state[(t & 1) ^ 1];      // linear layout in global
            __stcg(sn + c0 * 8 + b, n0);
            __stcg(sn + (c0 + 1) * 8 + b, n1);
            float2 ov;                              // PowerIndex: even col squared
            ov.x = n0 * n0;
            ov.y = n1;
            *(float2*)(out + ((size_t)(b * TT + t)) * OUTF + DD + c0) = ov;
        }
        __syncthreads();

        // Single cumulative release per CTA (orders all epilogue stores)
        if (tid == 0) {
            asm volatile("red.release.gpu.global.add.u32 [%0], %1;"
                         :: "l"(&g_step_count), "r"(1u) : "memory");
        }
    }
}

__global__ void copy_inputs_kernel(const float4* __restrict__ in, float* __restrict__ out) {
    int idx = blockIdx.x * blockDim.x + threadIdx.x;
    if (idx < BB * TT * DD / 4) {
        int bt = idx >> 5;  // 32 float4 per (b,t) row
        int q = idx & 31;
        float4 v = in[idx];
        *(float4*)(out + (size_t)bt * OUTF + q * 4) = v;
    }
}

extern "C" void kernel_launch(void* const* d_in, const int* in_sizes, int n_in,
                              void* d_out, int out_size) {
    const float* inputs = (const float*)d_in[0];
    const float* w_in   = (const float*)d_in[1];
    const float* b_in   = (const float*)d_in[2];
    const float* w_res  = (const float*)d_in[3];
    float* out = (float*)d_out;

    cudaFuncSetAttribute(esn_kernel, cudaFuncAttributeMaxDynamicSharedMemorySize, SMEM_BYTES);

    copy_inputs_kernel<<<(BB * TT * DD / 4 + 255) / 256, 256>>>((const float4*)inputs, out);
    esn_kernel<<<NCTA, NTHR, SMEM_BYTES>>>(inputs, w_in, b_in, w_res, out);
}

// round 9
// speedup vs baseline: 1.4884x; 1.2234x over previous
#include <cuda_runtime.h>
#include <math.h>

#define BB 8
#define TT 1024
#define DD 128
#define UU 2048
#define OUTF (DD + UU)
#define NCTA 256
#define COLS 16
#define KROWS 1024            // k rows per CTA
#define NTHR 256
#define NWARP 8

typedef unsigned long long ull;

// SMEM layout (floats)
#define W_FLOATS   (KROWS * COLS)   // 16384  w_res slice (64KB)
#define S_FLOATS   (KROWS * BB)     // 8192   state half (32KB)
#define WI_FLOATS  (DD * COLS)      // 2048   w_in slice (8KB, kh0 only)
#define BI_FLOATS  16
#define RED_ULL    (NWARP * 32)     // [8 warps][32 lanes]
#define SMEM_FLOATS (W_FLOATS + S_FLOATS + WI_FLOATS + BI_FLOATS + RED_ULL * 2)
#define SMEM_BYTES  (SMEM_FLOATS * 4)   // ~106.3 KB -> 2 CTAs/SM

__device__ float g_state[2][UU * BB];   // ping-pong state, linear [k][b]
__device__ unsigned g_bar_count;        // init barrier
__device__ unsigned g_bar_gen;          // monotone across replays
__device__ unsigned g_cnt[64];          // [0]=lo-half releases, [32]=hi-half (128B apart)
__device__ ull      g_part[128 * 64];   // pair partials [cg][64] f32x2
__device__ unsigned g_pflag[128 * 16];  // pair flags, 64B stride

__device__ __forceinline__ void cp16(unsigned dst, const void* src) {
    asm volatile("cp.async.cg.shared.global [%0], [%1], 16;" :: "r"(dst), "l"(src));
}
__device__ __forceinline__ void cp_commit() { asm volatile("cp.async.commit_group;"); }
template <int N>
__device__ __forceinline__ void cp_wait() {
    asm volatile("cp.async.wait_group %0;" :: "n"(N));
}
__device__ __forceinline__ void ffma2(ull& acc, ull a, ull b) {
    asm("fma.rn.f32x2 %0, %1, %2, %0;" : "+l"(acc) : "l"(a), "l"(b));
}
__device__ __forceinline__ ull dup2(float x) {
    ull r;
    unsigned xi = __float_as_uint(x);
    asm("mov.b64 %0, {%1, %1};" : "=l"(r) : "r"(xi));
    return r;
}
__device__ __forceinline__ ull padd2(ull a, ull b) {
    ull r;
    asm("add.rn.f32x2 %0, %1, %2;" : "=l"(r) : "l"(a), "l"(b));
    return r;
}
__device__ __forceinline__ ull bfly2(ull v, int m) {
    unsigned lo = (unsigned)v, hi = (unsigned)(v >> 32);
    lo = __shfl_xor_sync(0xffffffffu, lo, m);
    hi = __shfl_xor_sync(0xffffffffu, hi, m);
    ull r;
    asm("mov.b64 %0, {%1, %2};" : "=l"(r) : "r"(lo), "r"(hi));
    return r;
}
__device__ __forceinline__ unsigned acq(const unsigned* p) {
    unsigned v;
    asm volatile("ld.acquire.gpu.global.u32 %0, [%1];" : "=r"(v) : "l"(p));
    return v;
}
__device__ __forceinline__ void rel_add(unsigned* p) {
    asm volatile("red.release.gpu.global.add.u32 [%0], %1;" :: "l"(p), "r"(1u) : "memory");
}

// init-only grid barrier (proven pattern)
__device__ __forceinline__ void grid_barrier_init() {
    __syncthreads();
    if (threadIdx.x == 0) {
        __threadfence();
        unsigned gen;
        asm volatile("ld.acquire.gpu.u32 %0, [%1];" : "=r"(gen) : "l"(&g_bar_gen));
        if (atomicAdd(&g_bar_count, 1) == NCTA - 1) {
            g_bar_count = 0;
            asm volatile("st.release.gpu.u32 [%0], %1;" :: "l"(&g_bar_gen), "r"(gen + 1)
                         : "memory");
        } else {
            unsigned cur;
            do {
                asm volatile("ld.acquire.gpu.u32 %0, [%1];" : "=r"(cur) : "l"(&g_bar_gen));
                if (cur != gen) break;
                __nanosleep(32);
            } while (true);
        }
    }
    __syncthreads();
}

__global__ void __launch_bounds__(NTHR, 2)
esn_kernel(const float* __restrict__ inputs, const float* __restrict__ w_in_g,
           const float* __restrict__ b_in_g, const float* __restrict__ w_res_g,
           float* __restrict__ out) {
    extern __shared__ float smem[];
    float* w_sh  = smem;                    // [1024][16] chunk-swizzled (local rows)
    float* s_sh  = w_sh + W_FLOATS;         // [1024][8] granule-swizzled (local rows)
    float* wi_sh = s_sh + S_FLOATS;         // [128][16] chunk-swizzled
    float* bi_sh = wi_sh + WI_FLOATS;       // [16]
    ull* red = (ull*)(bi_sh + BI_FLOATS);   // [8 warps][32]

    const int tid = threadIdx.x;
    const int cta = blockIdx.x;
    const int cg  = cta >> 1;               // col-group 0..127
    const int kh  = cta & 1;                // k-half: rows [kh*1024, +1024)
    const int col0 = cg * COLS;
    // epilogue CTA = the k-half whose rows contain its own columns
    const int epi_kh = (cg >= 64) ? 1 : 0;
    const bool is_epi = (kh == epi_kh);

    if (cta == 0 && tid == 0) { g_cnt[0] = 0; g_cnt[32] = 0; }  // fresh per replay
    if (!is_epi && tid == 0) g_pflag[cg * 16] = 0;              // sender resets its flag

    // Stage w_res slice: local row lr -> global row kh*1024+lr; 16B chunk c of
    // row lr stored at position c ^ ((lr>>1)&3)  -> conflict-free LDS.128.
    for (int lr = tid; lr < KROWS; lr += NTHR) {
        const float4* src = (const float4*)(w_res_g + (size_t)(kh * KROWS + lr) * UU + col0);
        int m = (lr >> 1) & 3;
        float4* dst = (float4*)(w_sh + lr * COLS);
        dst[0 ^ m] = src[0]; dst[1 ^ m] = src[1];
        dst[2 ^ m] = src[2]; dst[3 ^ m] = src[3];
    }
    if (kh == 0 && tid < DD) {
        int r = tid;
        const float4* src = (const float4*)(w_in_g + (size_t)r * UU + col0);
        int m = (r >> 1) & 3;
        float4* dst = (float4*)(wi_sh + r * COLS);
        dst[0 ^ m] = src[0]; dst[1 ^ m] = src[1];
        dst[2 ^ m] = src[2]; dst[3 ^ m] = src[3];
    }
    if (tid < COLS) bi_sh[tid] = b_in_g[col0 + tid];

    // Zero initial state (buffer 0)
    for (int i = cta * NTHR + tid; i < UU * BB; i += NCTA * NTHR) g_state[0][i] = 0.0f;

    grid_barrier_init();

    // Decomposition: 128 k-slices x 2 col-halves; thread rows lr = ks + 128*i.
    const int ks = tid & 127;
    const int jh = tid >> 7;
    const int warp = tid >> 5;
    const int lane = tid & 31;
    const int mk = (ks >> 1) & 3;                 // weight chunk-swizzle key
    const unsigned w_off0 = (unsigned)(4 * ks + ((2 * jh) ^ mk)) * 16;
    const unsigned w_off1 = (unsigned)(4 * ks + ((2 * jh + 1) ^ mk)) * 16;
    const unsigned G0 = 2 * ks, G1 = 2 * ks + 1;  // local state granules, i=0
    const unsigned sA_off = (G0 ^ ((G0 >> 3) & 1)) * 16;
    const unsigned sB_off = (G1 ^ ((G1 >> 3) & 1)) * 16;
    const unsigned s_base = (unsigned)__cvta_generic_to_shared(s_sh);
    unsigned* my_cnt = &g_cnt[kh * 32];           // gate on own row-half producers

    for (int t = 0; t < TT; ++t) {
        // x_t (kh0 only, d = ks): independent of state, in flight over the gate
        float xv[8];
        if (kh == 0) {
#pragma unroll
            for (int b = 0; b < 8; ++b)
                xv[b] = __ldg(inputs + ((size_t)(b * TT + t)) * DD + ks);
        }

        // Step gate: 64 epilogue CTAs of this row-half released step t-1
        if (tid == 0) {
            const unsigned target = 64u * (unsigned)t;
            unsigned v = acq(my_cnt);
            while (v < target) { __nanosleep(20); v = acq(my_cnt); }
        }
        __syncthreads();

        // Load this CTA's state half (32KB): 8 waves of 256 granules, 4 groups.
        const float* sg = g_state[t & 1] + kh * S_FLOATS;
#pragma unroll
        for (int w = 0; w < 8; ++w) {
            unsigned g = (unsigned)tid + 256u * w;
            cp16(s_base + ((g ^ ((g >> 3) & 1)) << 4), sg + g * 4);
            if (w & 1) cp_commit();
        }

        ull acc[8][4];
#pragma unroll
        for (int a1 = 0; a1 < 8; ++a1)
#pragma unroll
            for (int a2 = 0; a2 < 4; ++a2) acc[a1][a2] = 0ULL;

        // Input projection (kh0, overlaps chunk-0 flight); wi row = ks
        if (kh == 0) {
            ulonglong2 u0 = *(const ulonglong2*)((const char*)wi_sh + w_off0);
            ulonglong2 u1 = *(const ulonglong2*)((const char*)wi_sh + w_off1);
#pragma unroll
            for (int b = 0; b < 8; ++b) {
                ull d = dup2(xv[b]);
                ffma2(acc[b][0], u0.x, d); ffma2(acc[b][1], u0.y, d);
                ffma2(acc[b][2], u1.x, d); ffma2(acc[b][3], u1.y, d);
            }
        }

#define ROW(i)                                                                          \
    {                                                                                   \
        float4 sA = *(const float4*)((const char*)s_sh + sA_off + (i) * 4096);          \
        float4 sB = *(const float4*)((const char*)s_sh + sB_off + (i) * 4096);          \
        ulonglong2 u0 = *(const ulonglong2*)((const char*)w_sh + w_off0 + (i) * 8192);  \
        ulonglong2 u1 = *(const ulonglong2*)((const char*)w_sh + w_off1 + (i) * 8192);  \
        ull d;                                                                          \
        d = dup2(sA.x);                                                                 \
        ffma2(acc[0][0], u0.x, d); ffma2(acc[0][1], u0.y, d);                           \
        ffma2(acc[0][2], u1.x, d); ffma2(acc[0][3], u1.y, d);                           \
        d = dup2(sA.y);                                                                 \
        ffma2(acc[1][0], u0.x, d); ffma2(acc[1][1], u0.y, d);                           \
        ffma2(acc[1][2], u1.x, d); ffma2(acc[1][3], u1.y, d);                           \
        d = dup2(sA.z);                                                                 \
        ffma2(acc[2][0], u0.x, d); ffma2(acc[2][1], u0.y, d);                           \
        ffma2(acc[2][2], u1.x, d); ffma2(acc[2][3], u1.y, d);                           \
        d = dup2(sA.w);                                                                 \
        ffma2(acc[3][0], u0.x, d); ffma2(acc[3][1], u0.y, d);                           \
        ffma2(acc[3][2], u1.x, d); ffma2(acc[3][3], u1.y, d);                           \
        d = dup2(sB.x);                                                                 \
        ffma2(acc[4][0], u0.x, d); ffma2(acc[4][1], u0.y, d);                           \
        ffma2(acc[4][2], u1.x, d); ffma2(acc[4][3], u1.y, d);                           \
        d = dup2(sB.y);                                                                 \
        ffma2(acc[5][0], u0.x, d); ffma2(acc[5][1], u0.y, d);                           \
        ffma2(acc[5][2], u1.x, d); ffma2(acc[5][3], u1.y, d);                           \
        d = dup2(sB.z);                                                                 \
        ffma2(acc[6][0], u0.x, d); ffma2(acc[6][1], u0.y, d);                           \
        ffma2(acc[6][2], u1.x, d); ffma2(acc[6][3], u1.y, d);                           \
        d = dup2(sB.w);                                                                 \
        ffma2(acc[7][0], u0.x, d); ffma2(acc[7][1], u0.y, d);                           \
        ffma2(acc[7][2], u1.x, d); ffma2(acc[7][3], u1.y, d);                           \
    }

        // Pipelined dot: group c covers local rows [256c, 256c+256) = i = 2c, 2c+1
        cp_wait<3>(); __syncthreads();
        ROW(0) ROW(1)
        cp_wait<2>(); __syncthreads();
        ROW(2) ROW(3)
        cp_wait<1>(); __syncthreads();
        ROW(4) ROW(5)
        cp_wait<0>(); __syncthreads();
        ROW(6) ROW(7)
#undef ROW

        // Warp butterfly: 32 accs/lane -> 1; lane L holds acc index brev5(L)
        {
            ull* A = &acc[0][0];
#pragma unroll
            for (int lev = 0; lev < 5; ++lev) {
                const int mm = 1 << lev;
                const int n = 16 >> lev;
                const bool up = (lane & mm) != 0;
#pragma unroll
                for (int q = 0; q < n; ++q) {
                    ull send = up ? A[q] : A[q + n];
                    ull recv = bfly2(send, mm);
                    ull keep = up ? A[q + n] : A[q];
                    A[q] = padd2(keep, recv);
                }
            }
            red[warp * 32 + lane] = A[0];
        }
        __syncthreads();

        // Final reduce over 4 warps per col-half; pair combine; epilogue or send.
        if (tid < 64) {
            const int jh2 = tid >> 5;
            const int ln = tid & 31;
            ull v = red[(jh2 * 4) * 32 + ln];
#pragma unroll
            for (int w = 1; w < 4; ++w) v = padd2(v, red[(jh2 * 4 + w) * 32 + ln]);

            if (!is_epi) {
                __stcg(&g_part[cg * 64 + tid], v);   // sender: partial to L2
            } else {
                // bit-reversed mapping from butterfly
                const int a = ((ln & 1) << 4) | ((ln & 2) << 2) | (ln & 4) |
                              ((ln & 8) >> 2) | ((ln & 16) >> 4);
                const int b = a >> 2;
                const int jl = jh2 * 8 + 2 * (a & 3);
                const int c0 = col0 + jl;
                // old state from own SMEM (epi CTA's rows contain its columns)
                const int lr0 = c0 - kh * KROWS;
                unsigned H0 = (unsigned)(2 * lr0 + (b >> 2));
                unsigned H1 = H0 + 2;
                float so0 = s_sh[(H0 ^ ((H0 >> 3) & 1)) * 4 + (b & 3)];
                float so1 = s_sh[(H1 ^ ((H1 >> 3) & 1)) * 4 + (b & 3)];
                // wait for partner partial
                const unsigned ft = (unsigned)t + 1u;
                unsigned fv = acq(&g_pflag[cg * 16]);
                while (fv < ft) { __nanosleep(20); fv = acq(&g_pflag[cg * 16]); }
                v = padd2(v, __ldcg(&g_part[cg * 64 + tid]));
                float pre0 = __uint_as_float((unsigned)v) + bi_sh[jl];
                float pre1 = __uint_as_float((unsigned)(v >> 32)) + bi_sh[jl + 1];
                float n0 = 0.5f * so0 + 0.5f * tanhf(pre0);
                float n1 = 0.5f * so1 + 0.5f * tanhf(pre1);
                float* sn = g_state[(t & 1) ^ 1];
                __stcg(sn + c0 * 8 + b, n0);
                __stcg(sn + (c0 + 1) * 8 + b, n1);
                float2 ov;                          // PowerIndex: even col squared
                ov.x = n0 * n0;
                ov.y = n1;
                *(float2*)(out + ((size_t)(b * TT + t)) * OUTF + DD + c0) = ov;
            }
        }
        __syncthreads();

        // Single cumulative release per CTA (sync above orders all 64 threads' stores)
        if (tid == 0) {
            if (is_epi) rel_add(&g_cnt[epi_kh * 32]);  // state published
            else        rel_add(&g_pflag[cg * 16]);    // partial published
        }
    }
}

__global__ void copy_inputs_kernel(const float4* __restrict__ in, float* __restrict__ out) {
    int idx = blockIdx.x * blockDim.x + threadIdx.x;
    if (idx < BB * TT * DD / 4) {
        int bt = idx >> 5;  // 32 float4 per (b,t) row
        int q = idx & 31;
        float4 v = in[idx];
        *(float4*)(out + (size_t)bt * OUTF + q * 4) = v;
    }
}

extern "C" void kernel_launch(void* const* d_in, const int* in_sizes, int n_in,
                              void* d_out, int out_size) {
    const float* inputs = (const float*)d_in[0];
    const float* w_in   = (const float*)d_in[1];
    const float* b_in   = (const float*)d_in[2];
    const float* w_res  = (const float*)d_in[3];
    float* out = (float*)d_out;

    cudaFuncSetAttribute(esn_kernel, cudaFuncAttributeMaxDynamicSharedMemorySize, SMEM_BYTES);

    copy_inputs_kernel<<<(BB * TT * DD / 4 + 255) / 256, 256>>>((const float4*)inputs, out);
    esn_kernel<<<NCTA, NTHR, SMEM_BYTES>>>(inputs, w_in, b_in, w_res, out);
}

// round 11
// speedup vs baseline: 1.8026x; 1.2111x over previous
#include <cuda_runtime.h>
#include <math.h>

#define BB 8
#define TT 1024
#define DD 128
#define UU 2048
#define OUTF (DD + UU)
#define NCTA 128
#define COLS 16
#define NTHR 512
#define NWARP 16

typedef unsigned long long ull;

// SMEM layout (floats)
#define W_FLOATS   (UU * COLS)    // 32768  w_res slice, 64B rows, chunk-swizzled
#define S_FLOATS   (UU * BB)      // 16384  state, 16B-granule swizzled
#define WI_FLOATS  (DD * COLS)    // 2048   w_in slice, same swizzle
#define BI_FLOATS  16
#define RED_ULL    (NWARP * 64)   // [16 warps][64 og] f32x2 partials
#define SMEM_FLOATS (W_FLOATS + S_FLOATS + WI_FLOATS + BI_FLOATS + RED_ULL * 2)
#define SMEM_BYTES  (SMEM_FLOATS * 4)   // ~213 KB < 227 KB

__device__ float g_state[2][UU * BB];   // ping-pong state, linear [k][b]
__device__ unsigned g_bar_count;        // init barrier
__device__ unsigned g_bar_gen;          // monotone across replays
__device__ unsigned g_step_count;       // 1 release per CTA per step

__device__ __forceinline__ void cp16(unsigned dst, const void* src) {
    asm volatile("cp.async.cg.shared.global [%0], [%1], 16;" :: "r"(dst), "l"(src));
}
__device__ __forceinline__ void cp_commit() { asm volatile("cp.async.commit_group;"); }
template <int N>
__device__ __forceinline__ void cp_wait() {
    asm volatile("cp.async.wait_group %0;" :: "n"(N));
}
// packed fp32x2 ops — ptxas never emits these from C++
__device__ __forceinline__ void ffma2(ull& acc, ull a, ull b) {
    asm("fma.rn.f32x2 %0, %1, %2, %0;" : "+l"(acc) : "l"(a), "l"(b));
}
__device__ __forceinline__ ull dup2(float x) {
    ull r;
    unsigned xi = __float_as_uint(x);
    asm("mov.b64 %0, {%1, %1};" : "=l"(r) : "r"(xi));
    return r;
}
__device__ __forceinline__ ull padd2(ull a, ull b) {
    ull r;
    asm("add.rn.f32x2 %0, %1, %2;" : "=l"(r) : "l"(a), "l"(b));
    return r;
}
__device__ __forceinline__ ull bfly2(ull v, int m) {
    unsigned lo = (unsigned)v, hi = (unsigned)(v >> 32);
    lo = __shfl_xor_sync(0xffffffffu, lo, m);
    hi = __shfl_xor_sync(0xffffffffu, hi, m);
    ull r;
    asm("mov.b64 %0, {%1, %2};" : "=l"(r) : "r"(lo), "r"(hi));
    return r;
}

// init-only grid barrier (proven pattern)
__device__ __forceinline__ void grid_barrier_init() {
    __syncthreads();
    if (threadIdx.x == 0) {
        __threadfence();
        unsigned gen;
        asm volatile("ld.acquire.gpu.u32 %0, [%1];" : "=r"(gen) : "l"(&g_bar_gen));
        if (atomicAdd(&g_bar_count, 1) == NCTA - 1) {
            g_bar_count = 0;
            asm volatile("st.release.gpu.u32 [%0], %1;" :: "l"(&g_bar_gen), "r"(gen + 1)
                         : "memory");
        } else {
            unsigned cur;
            do {
                asm volatile("ld.acquire.gpu.u32 %0, [%1];" : "=r"(cur) : "l"(&g_bar_gen));
                if (cur != gen) break;
                __nanosleep(32);
            } while (true);
        }
    }
    __syncthreads();
}

__global__ void __launch_bounds__(NTHR, 1)
esn_kernel(const float* __restrict__ inputs, const float* __restrict__ w_in_g,
           const float* __restrict__ b_in_g, const float* __restrict__ w_res_g,
           float* __restrict__ out) {
    extern __shared__ float smem[];
    float* w_sh  = smem;                    // [2048][16] chunk-swizzled
    float* s_sh  = w_sh + W_FLOATS;         // [2048][8] granule-swizzled
    float* wi_sh = s_sh + S_FLOATS;         // [128][16] chunk-swizzled
    float* bi_sh = wi_sh + WI_FLOATS;       // [16]
    ull* red = (ull*)(bi_sh + BI_FLOATS);   // [16 warps][64]

    const int tid = threadIdx.x;
    const int cta = blockIdx.x;
    const int col0 = cta * COLS;

    if (cta == 0 && tid == 0) g_step_count = 0;   // fresh epoch per launch/replay

    // Stage w_res slice; 16B chunk c of row r stored at position c ^ ((r>>1)&3)
    for (int r = tid; r < UU; r += NTHR) {
        const float4* src = (const float4*)(w_res_g + (size_t)r * UU + col0);
        int m = (r >> 1) & 3;
        float4* dst = (float4*)(w_sh + r * COLS);
        dst[0 ^ m] = src[0]; dst[1 ^ m] = src[1];
        dst[2 ^ m] = src[2]; dst[3 ^ m] = src[3];
    }
    if (tid < DD) {
        int r = tid;
        const float4* src = (const float4*)(w_in_g + (size_t)r * UU + col0);
        int m = (r >> 1) & 3;
        float4* dst = (float4*)(wi_sh + r * COLS);
        dst[0 ^ m] = src[0]; dst[1 ^ m] = src[1];
        dst[2 ^ m] = src[2]; dst[3 ^ m] = src[3];
    }
    if (tid < COLS) bi_sh[tid] = b_in_g[col0 + tid];

    // Zero initial state (buffer 0)
    for (int i = cta * NTHR + tid; i < UU * BB; i += NCTA * NTHR) g_state[0][i] = 0.0f;

    grid_barrier_init();

    // Decomposition: paired lanes share a k-slice (state reads broadcast);
    // jh = column half (8 cols each). Thread rows: ks + 256*i.
    const int warp = tid >> 5;
    const int lane = tid & 31;
    const int jh = lane & 1;
    const int ks = (warp << 4) + (lane >> 1);     // 0..255
    const int mk = (ks >> 1) & 3;                 // weight chunk-swizzle key
    const unsigned w_off0 = (unsigned)(4 * ks + ((2 * jh) ^ mk)) * 16;
    const unsigned w_off1 = (unsigned)(4 * ks + ((2 * jh + 1) ^ mk)) * 16;
    const unsigned gA = 2 * ks, gB = 2 * ks + 1;  // state granules of row ks (i=0)
    const unsigned sA_off = (gA ^ ((gA >> 3) & 1)) * 16;
    const unsigned sB_off = (gB ^ ((gB >> 3) & 1)) * 16;
    // butterfly landing map: lane bit1->+16, bit2->+8, bit3->+4, bit4->+2
    const int base = (((lane >> 1) & 1) << 4) | (((lane >> 2) & 1) << 3) |
                     (((lane >> 3) & 1) << 2) | (((lane >> 4) & 1) << 1);
    const unsigned s_base = (unsigned)__cvta_generic_to_shared(s_sh);

    for (int t = 0; t < TT; ++t) {
        // x_t for proj rows (ks<128): independent of state, in flight over the gate
        float xv[8];
        if (ks < DD) {
#pragma unroll
            for (int b = 0; b < 8; ++b)
                xv[b] = __ldg(inputs + ((size_t)(b * TT + t)) * DD + ks);
        }

        // Step gate: all 128 CTAs released step t-1 (1 release per CTA)
        if (tid == 0) {
            const unsigned target = 128u * (unsigned)t;
            unsigned v;
            do {
                asm volatile("ld.acquire.gpu.global.u32 %0, [%1];"
                             : "=r"(v) : "l"(&g_step_count));
            } while (v < target);
        }
        __syncthreads();

        // Broadcast state: 4 chunks x 16KB; granule g stored at g ^ ((g>>3)&1)
        const float* sg = g_state[t & 1];
#pragma unroll
        for (int c = 0; c < 4; ++c) {
            int g0 = c * 1024 + tid;
            cp16(s_base + ((unsigned)(g0 ^ ((g0 >> 3) & 1)) << 4), sg + g0 * 4);
            int g1 = g0 + 512;
            cp16(s_base + ((unsigned)(g1 ^ ((g1 >> 3) & 1)) << 4), sg + g1 * 4);
            cp_commit();
        }

        ull acc[8][4];
#pragma unroll
        for (int a1 = 0; a1 < 8; ++a1)
#pragma unroll
            for (int a2 = 0; a2 < 4; ++a2) acc[a1][a2] = 0ULL;

        // Input projection (overlaps chunk-0 flight); wi row = ks, same offsets
        if (ks < DD) {
            ulonglong2 u0 = *(const ulonglong2*)((const char*)wi_sh + w_off0);
            ulonglong2 u1 = *(const ulonglong2*)((const char*)wi_sh + w_off1);
#pragma unroll
            for (int b = 0; b < 8; ++b) {
                ull d = dup2(xv[b]);
                ffma2(acc[b][0], u0.x, d); ffma2(acc[b][1], u0.y, d);
                ffma2(acc[b][2], u1.x, d); ffma2(acc[b][3], u1.y, d);
            }
        }

#define ROW(i)                                                                          \
    {                                                                                   \
        float4 sA = *(const float4*)((const char*)s_sh + sA_off + (i) * 8192);          \
        float4 sB = *(const float4*)((const char*)s_sh + sB_off + (i) * 8192);          \
        ulonglong2 u0 = *(const ulonglong2*)((const char*)w_sh + w_off0 + (i) * 16384); \
        ulonglong2 u1 = *(const ulonglong2*)((const char*)w_sh + w_off1 + (i) * 16384); \
        ull d;                                                                          \
        d = dup2(sA.x);                                                                 \
        ffma2(acc[0][0], u0.x, d); ffma2(acc[0][1], u0.y, d);                           \
        ffma2(acc[0][2], u1.x, d); ffma2(acc[0][3], u1.y, d);                           \
        d = dup2(sA.y);                                                                 \
        ffma2(acc[1][0], u0.x, d); ffma2(acc[1][1], u0.y, d);                           \
        ffma2(acc[1][2], u1.x, d); ffma2(acc[1][3], u1.y, d);                           \
        d = dup2(sA.z);                                                                 \
        ffma2(acc[2][0], u0.x, d); ffma2(acc[2][1], u0.y, d);                           \
        ffma2(acc[2][2], u1.x, d); ffma2(acc[2][3], u1.y, d);                           \
        d = dup2(sA.w);                                                                 \
        ffma2(acc[3][0], u0.x, d); ffma2(acc[3][1], u0.y, d);                           \
        ffma2(acc[3][2], u1.x, d); ffma2(acc[3][3], u1.y, d);                           \
        d = dup2(sB.x);                                                                 \
        ffma2(acc[4][0], u0.x, d); ffma2(acc[4][1], u0.y, d);                           \
        ffma2(acc[4][2], u1.x, d); ffma2(acc[4][3], u1.y, d);                           \
        d = dup2(sB.y);                                                                 \
        ffma2(acc[5][0], u0.x, d); ffma2(acc[5][1], u0.y, d);                           \
        ffma2(acc[5][2], u1.x, d); ffma2(acc[5][3], u1.y, d);                           \
        d = dup2(sB.z);                                                                 \
        ffma2(acc[6][0], u0.x, d); ffma2(acc[6][1], u0.y, d);                           \
        ffma2(acc[6][2], u1.x, d); ffma2(acc[6][3], u1.y, d);                           \
        d = dup2(sB.w);                                                                 \
        ffma2(acc[7][0], u0.x, d); ffma2(acc[7][1], u0.y, d);                           \
        ffma2(acc[7][2], u1.x, d); ffma2(acc[7][3], u1.y, d);                           \
    }

        // Pipelined dot: chunk c holds rows [512c, 512c+512) = i = 2c, 2c+1
        cp_wait<3>(); __syncthreads();
        ROW(0) ROW(1)
        cp_wait<2>(); __syncthreads();
        ROW(2) ROW(3)
        cp_wait<1>(); __syncthreads();
        ROW(4) ROW(5)
        cp_wait<0>(); __syncthreads();
        ROW(6) ROW(7)
#undef ROW

        // 4-level butterfly over masks 2,4,8,16 (mask-1 partner owns the other
        // column half, not summed). Lane ends with og (jh, base), (jh, base+1).
        {
            ull* A = &acc[0][0];
#pragma unroll
            for (int lev = 0; lev < 4; ++lev) {
                const int mm = 2 << lev;
                const int n = 16 >> lev;
                const bool up = (lane & mm) != 0;
#pragma unroll
                for (int q = 0; q < n; ++q) {
                    ull send = up ? A[q] : A[q + n];
                    ull recv = bfly2(send, mm);
                    ull keep = up ? A[q + n] : A[q];
                    A[q] = padd2(keep, recv);
                }
            }
            red[warp * 64 + jh * 32 + base] = A[0];
            red[warp * 64 + jh * 32 + base + 1] = A[1];
        }
        __syncthreads();

        // Final reduce over 16 warps + epilogue (64 threads)
        if (tid < 64) {
            ull v = red[tid];
#pragma unroll
            for (int w = 1; w < NWARP; ++w) v = padd2(v, red[w * 64 + tid]);
            const int jh2 = tid >> 5;
            const int a = tid & 31;
            const int b = a >> 2;
            const int p = a & 3;
            const int jl = jh2 * 8 + 2 * p;
            const int c0 = col0 + jl;
            float pre0 = __uint_as_float((unsigned)v) + bi_sh[jl];
            float pre1 = __uint_as_float((unsigned)(v >> 32)) + bi_sh[jl + 1];
            unsigned G0 = (unsigned)(2 * c0 + (b >> 2));
            unsigned G1 = G0 + 2;
            float so0 = s_sh[(G0 ^ ((G0 >> 3) & 1)) * 4 + (b & 3)];
            float so1 = s_sh[(G1 ^ ((G1 >> 3) & 1)) * 4 + (b & 3)];
            float n0 = 0.5f * so0 + 0.5f * tanhf(pre0);
            float n1 = 0.5f * so1 + 0.5f * tanhf(pre1);
            float* sn = g_state[(t & 1) ^ 1];      // linear layout in global
            __stcg(sn + c0 * 8 + b, n0);
            __stcg(sn + (c0 + 1) * 8 + b, n1);
            float2 ov;                              // PowerIndex: even col squared
            ov.x = n0 * n0;
            ov.y = n1;
            *(float2*)(out + ((size_t)(b * TT + t)) * OUTF + DD + c0) = ov;
        }
        __syncthreads();   // epilogue done before release; protects s_sh reuse

        // Single cumulative release per CTA (bar orders all 64 threads' stores)
        if (tid == 0) {
            asm volatile("red.release.gpu.global.add.u32 [%0], %1;"
                         :: "l"(&g_step_count), "r"(1u) : "memory");
        }
    }
}

__global__ void copy_inputs_kernel(const float4* __restrict__ in, float* __restrict__ out) {
    int idx = blockIdx.x * blockDim.x + threadIdx.x;
    if (idx < BB * TT * DD / 4) {
        int bt = idx >> 5;  // 32 float4 per (b,t) row
        int q = idx & 31;
        float4 v = in[idx];
        *(float4*)(out + (size_t)bt * OUTF + q * 4) = v;
    }
}

extern "C" void kernel_launch(void* const* d_in, const int* in_sizes, int n_in,
                              void* d_out, int out_size) {
    const float* inputs = (const float*)d_in[0];
    const float* w_in   = (const float*)d_in[1];
    const float* b_in   = (const float*)d_in[2];
    const float* w_res  = (const float*)d_in[3];
    float* out = (float*)d_out;

    cudaFuncSetAttribute(esn_kernel, cudaFuncAttributeMaxDynamicSharedMemorySize, SMEM_BYTES);

    copy_inputs_kernel<<<(BB * TT * DD / 4 + 255) / 256, 256>>>((const float4*)inputs, out);
    esn_kernel<<<NCTA, NTHR, SMEM_BYTES>>>(inputs, w_in, b_in, w_res, out);
}